// round 13
// baseline (speedup 1.0000x reference)
#include <cuda_runtime.h>
#include <math.h>

// Problem constants
#define E   4096
#define BB  8          // batch
#define TJ  512        // columns per block in K1 (256 threads * float2)
#define TK  32         // rows per split in K1 (best measured K1 shape)
#define NSPLIT (E / TK)   // 128 row-splits
#define NCOLB  (E / TJ)   // 8 column blocks

// Deterministic split-K scratch: [NSPLIT][BB][E] fp32 = 16 MB (evict-first)
__device__ float g_scratch[(size_t)NSPLIT * BB * E];

// L2 evict-last load via createpolicy + cache_hint (legal for .v2.f32).
__device__ __forceinline__ float2 ldg_el_f2(const float2* p) {
    float2 v;
    asm("{\n\t"
        ".reg .b64 pol;\n\t"
        "createpolicy.fractional.L2::evict_last.b64 pol, 1.0;\n\t"
        "ld.global.L2::cache_hint.v2.f32 {%0,%1}, [%2], pol;\n\t"
        "}"
        : "=f"(v.x), "=f"(v.y) : "l"(p));
    return v;
}

// ---------------------------------------------------------------------------
// K1 (stable 39us shape): stream w/alpha/hebb once (192 MB).
// Block: 32 rows x 512 cols, float2/thread, 64 regs, 4 blocks/SM, grid=1024.
// w/alpha: __ldcs (evict-first). hebb: evict_last (stay in L2 for K3).
// scratch: __stcs (evict-first; parallel K2 absorbs the DRAM round trip).
// ---------------------------------------------------------------------------
__global__ __launch_bounds__(256, 4)
void k1_partial_gemm(const float* __restrict__ yin,
                     const float* __restrict__ hebb,
                     const float* __restrict__ w,
                     const float* __restrict__ alpha)
{
    const int cb  = blockIdx.x;            // 0..NCOLB-1
    const int rb  = blockIdx.y;            // 0..NSPLIT-1
    const int tid = threadIdx.x;           // 0..255
    const int j0  = cb * TJ + tid * 2;     // this thread's 2 columns
    const int k0  = rb * TK;

    // Stage yin[b, k0:k0+TK] in smem (8*32 = 256 floats, one per thread)
    __shared__ float yin_s[BB][TK];
    {
        int b = tid / TK, k = tid % TK;    // tid < 256 = BB*TK exactly
        yin_s[b][k] = yin[(size_t)b * E + k0 + k];
    }
    __syncthreads();

    float accx[BB], accy[BB];
#pragma unroll
    for (int b = 0; b < BB; b++) { accx[b] = 0.f; accy[b] = 0.f; }

    const size_t base0 = (size_t)k0 * E + j0;
    const float2* wp = (const float2*)(w     + base0);
    const float2* ap = (const float2*)(alpha + base0);
    const float2* hp = (const float2*)(hebb  + base0);
    const int strideV = E / 2;             // float2 row stride

    // Depth-2 pipeline: rows k and k+1 in flight
    float2 w0 = __ldcs(wp);
    float2 a0 = __ldcs(ap);
    float2 h0 = ldg_el_f2(hp);
    float2 w1 = __ldcs(wp + strideV);
    float2 a1 = __ldcs(ap + strideV);
    float2 h1 = ldg_el_f2(hp + strideV);

#pragma unroll 8
    for (int k = 0; k < TK; k++) {
        float2 wn, an, hn;
        if (k + 2 < TK) {
            const int off = (k + 2) * strideV;
            wn = __ldcs(wp + off);
            an = __ldcs(ap + off);
            hn = ldg_el_f2(hp + off);
        }

        const float mx = fmaf(a0.x, h0.x, w0.x);
        const float my = fmaf(a0.y, h0.y, w0.y);
#pragma unroll
        for (int b = 0; b < BB; b++) {
            const float yv = yin_s[b][k];
            accx[b] = fmaf(yv, mx, accx[b]);
            accy[b] = fmaf(yv, my, accy[b]);
        }

        w0 = w1; a0 = a1; h0 = h1;
        w1 = wn; a1 = an; h1 = hn;
    }

    // Evict-first scratch stores: do NOT displace hebb from L2
#pragma unroll
    for (int b = 0; b < BB; b++) {
        float2 v = make_float2(accx[b], accy[b]);
        __stcs((float2*)(g_scratch + ((size_t)rb * BB + b) * E + j0), v);
    }
}

// ---------------------------------------------------------------------------
// K2 (parallel reduction): 1024 blocks x 256 threads.
// Block owns 32 consecutive outputs; warp w sums splits [w*16, w*16+16)
// with coalesced 128B loads; 8x32 smem reduce; warp 0 adds input + tanh.
// Scratch read with __ldcs (single use, don't pollute L2).
// ---------------------------------------------------------------------------
#define K2_OUTS 32
#define K2_SPW  (NSPLIT / 8)   // 16 splits per warp

__global__ __launch_bounds__(256)
void k2_yout(const float* __restrict__ input, float* __restrict__ yout)
{
    const int wid  = threadIdx.x >> 5;         // 0..7
    const int lane = threadIdx.x & 31;         // 0..31
    const int base = blockIdx.x * K2_OUTS;     // first output of this block
    const int idx  = base + lane;              // this lane's output elem

    float s = 0.f;
    const int r0 = wid * K2_SPW;
#pragma unroll
    for (int r = 0; r < K2_SPW; r++)
        s += __ldcs(&g_scratch[(size_t)(r0 + r) * BB * E + idx]);

    __shared__ float red[8][K2_OUTS];
    red[wid][lane] = s;
    __syncthreads();

    if (wid == 0) {
        float t = input[idx];
#pragma unroll
        for (int ww = 0; ww < 8; ww++)
            t += red[ww][lane];
        yout[idx] = tanhf(t);
    }
}

// ---------------------------------------------------------------------------
// K3: hebb_new = (1-eta)*hebb + eta * yin0 (outer) yout0.
// hebb should now be largely L2-resident (evict_last from K1).
// Reverse block order + __stcs output stores (don't evict unread hebb).
// ---------------------------------------------------------------------------
__global__ __launch_bounds__(256)
void k3_hebb(const float* __restrict__ hebb,
             const float* __restrict__ yin,    // row 0 used
             const float* __restrict__ eta,    // scalar
             const float* __restrict__ yout0,  // d_out row 0 (E floats)
             float* __restrict__ hebb_out)
{
    const float et    = eta[0];
    const float one_m = 1.0f - et;

    const int n4   = (E * E) / 4;
    const int rblk = gridDim.x - 1 - blockIdx.x;      // reverse block order
    const int t    = rblk * 256 + threadIdx.x;        // one float4 per thread
    if (t >= n4) return;

    const int row = t / (E / 4);
    const int c4  = t % (E / 4);
    const float s = et * yin[row];                    // eta * yin0[row]

    const float4 h = *(const float4*)(hebb + (size_t)t * 4);   // L2 hits
    const float4 y = __ldg((const float4*)(yout0 + (size_t)c4 * 4));
    float4 o;
    o.x = fmaf(one_m, h.x, s * y.x);
    o.y = fmaf(one_m, h.y, s * y.y);
    o.z = fmaf(one_m, h.z, s * y.z);
    o.w = fmaf(one_m, h.w, s * y.w);
    __stcs((float4*)(hebb_out + (size_t)t * 4), o);
}

// ---------------------------------------------------------------------------
// Launch: inputs in metadata order: input, yin, hebb, w, alpha, eta
// Output: [yout (8*4096) | hebb_new (4096*4096)] fp32
// ---------------------------------------------------------------------------
extern "C" void kernel_launch(void* const* d_in, const int* in_sizes, int n_in,
                              void* d_out, int out_size)
{
    const float* input = (const float*)d_in[0];
    const float* yin   = (const float*)d_in[1];
    const float* hebb  = (const float*)d_in[2];
    const float* w     = (const float*)d_in[3];
    const float* alpha = (const float*)d_in[4];
    const float* eta   = (const float*)d_in[5];

    float* out      = (float*)d_out;
    float* yout     = out;            // BB*E
    float* hebb_out = out + BB * E;   // E*E

    // K1: 8 col-blocks x 128 row-splits = 1024 blocks x 256 threads
    dim3 g1(NCOLB, NSPLIT);
    k1_partial_gemm<<<g1, 256>>>(yin, hebb, w, alpha);

    // K2: 32768 outputs / 32 per block = 1024 blocks
    k2_yout<<<(BB * E) / K2_OUTS, 256>>>(input, yout);

    // K3: E*E/4 float4 threads, reverse-ordered blocks
    const int n4 = (E * E) / 4;
    k3_hebb<<<(n4 + 255) / 256, 256>>>(hebb, yin, eta, yout, hebb_out);
}

// round 14
// speedup vs baseline: 1.0055x; 1.0055x over previous
#include <cuda_runtime.h>
#include <math.h>
#include <cstdint>

// Problem constants
#define E   4096
#define BB  8
#define TJ  512                 // columns per block
#define TK  32                  // rows per split
#define NSPLIT (E / TK)         // 128
#define NCOLB  (E / TJ)         // 8
#define NSTAGE 4                // pipeline depth
#define CHUNK  (TJ * 4)         // 2048 bytes per array per row

// Deterministic split-K scratch: [NSPLIT][BB][E] fp32 = 16 MB
__device__ float g_scratch[(size_t)NSPLIT * BB * E];

__device__ __forceinline__ uint32_t smem_u32(const void* p) {
    return (uint32_t)__cvta_generic_to_shared(p);
}
__device__ __forceinline__ void mbar_init(uint32_t m) {
    asm volatile("mbarrier.init.shared.b64 [%0], 1;" :: "r"(m) : "memory");
}
__device__ __forceinline__ void mbar_expect_tx(uint32_t m, uint32_t bytes) {
    asm volatile("mbarrier.arrive.expect_tx.shared.b64 _, [%0], %1;"
                 :: "r"(m), "r"(bytes) : "memory");
}
__device__ __forceinline__ void bulk_g2s(uint32_t dst, const void* src, uint32_t m) {
    asm volatile("cp.async.bulk.shared::cta.global.mbarrier::complete_tx::bytes "
                 "[%0], [%1], %2, [%3];"
                 :: "r"(dst), "l"(src), "r"((uint32_t)CHUNK), "r"(m) : "memory");
}
__device__ __forceinline__ void mbar_wait(uint32_t m, uint32_t phase) {
    asm volatile(
        "{\n\t"
        ".reg .pred P;\n"
        "LW%=:\n\t"
        "mbarrier.try_wait.parity.acquire.cta.shared::cta.b64 P, [%0], %1;\n\t"
        "@!P bra LW%=;\n\t"
        "}"
        :: "r"(m), "r"(phase) : "memory");
}

// ---------------------------------------------------------------------------
// K1: bulk-copy (TMA-style) producer/consumer pipeline.
// Block: 32 rows x 512 cols. Thread 0 issues 3x 2KB bulk copies per row into
// a 4-stage SMEM ring; 256 threads compute float2 FMAs from SMEM.
// Loads fully decoupled from the FMA dependency chain.
// ---------------------------------------------------------------------------
__global__ __launch_bounds__(256)
void k1_partial_gemm(const float* __restrict__ yin,
                     const float* __restrict__ hebb,
                     const float* __restrict__ w,
                     const float* __restrict__ alpha)
{
    __shared__ __align__(16) float stage[NSTAGE][3 * TJ];   // [w|a|h] per stage
    __shared__ __align__(16) float yin_s[TK][BB];           // transposed yin slice
    __shared__ __align__(8)  uint64_t mbar[NSTAGE];

    const int cb  = blockIdx.x;
    const int rb  = blockIdx.y;
    const int tid = threadIdx.x;
    const int k0  = rb * TK;
    const size_t colbase = (size_t)cb * TJ;

    // Stage yin transposed: yin_s[k][b] = yin[b, k0+k] (256 elems, 1/thread)
    {
        int k = tid >> 3, b = tid & 7;
        yin_s[k][b] = yin[(size_t)b * E + k0 + k];
    }
    if (tid == 0) {
        for (int s = 0; s < NSTAGE; s++) mbar_init(smem_u32(&mbar[s]));
    }
    __syncthreads();

    // Prologue: issue stages 0..NSTAGE-2
    if (tid == 0) {
        for (int k = 0; k < NSTAGE - 1; k++) {
            const int s = k;
            const uint32_t m = smem_u32(&mbar[s]);
            const size_t row = (size_t)(k0 + k) * E + colbase;
            mbar_expect_tx(m, 3 * CHUNK);
            bulk_g2s(smem_u32(&stage[s][0]),        w     + row, m);
            bulk_g2s(smem_u32(&stage[s][TJ]),       alpha + row, m);
            bulk_g2s(smem_u32(&stage[s][2 * TJ]),   hebb  + row, m);
        }
    }

    float accx[BB], accy[BB];
#pragma unroll
    for (int b = 0; b < BB; b++) { accx[b] = 0.f; accy[b] = 0.f; }

    for (int k = 0; k < TK; k++) {
        const int s = k & (NSTAGE - 1);
        mbar_wait(smem_u32(&mbar[s]), (k >> 2) & 1);

        const float2 wv = *(const float2*)&stage[s][tid * 2];
        const float2 av = *(const float2*)&stage[s][TJ + tid * 2];
        const float2 hv = *(const float2*)&stage[s][2 * TJ + tid * 2];
        const float mx = fmaf(av.x, hv.x, wv.x);
        const float my = fmaf(av.y, hv.y, wv.y);

        const float4 y0 = *(const float4*)&yin_s[k][0];   // batches 0-3 (broadcast)
        const float4 y1 = *(const float4*)&yin_s[k][4];   // batches 4-7 (broadcast)

        accx[0] = fmaf(y0.x, mx, accx[0]); accy[0] = fmaf(y0.x, my, accy[0]);
        accx[1] = fmaf(y0.y, mx, accx[1]); accy[1] = fmaf(y0.y, my, accy[1]);
        accx[2] = fmaf(y0.z, mx, accx[2]); accy[2] = fmaf(y0.z, my, accy[2]);
        accx[3] = fmaf(y0.w, mx, accx[3]); accy[3] = fmaf(y0.w, my, accy[3]);
        accx[4] = fmaf(y1.x, mx, accx[4]); accy[4] = fmaf(y1.x, my, accy[4]);
        accx[5] = fmaf(y1.y, mx, accx[5]); accy[5] = fmaf(y1.y, my, accy[5]);
        accx[6] = fmaf(y1.z, mx, accx[6]); accy[6] = fmaf(y1.z, my, accy[6]);
        accx[7] = fmaf(y1.w, mx, accx[7]); accy[7] = fmaf(y1.w, my, accy[7]);

        __syncthreads();   // all warps done with slot (k+NSTAGE-1)%NSTAGE's target

        if (tid == 0 && k + NSTAGE - 1 < TK) {
            const int kn = k + NSTAGE - 1;
            const int sn = kn & (NSTAGE - 1);
            const uint32_t m = smem_u32(&mbar[sn]);
            const size_t row = (size_t)(k0 + kn) * E + colbase;
            mbar_expect_tx(m, 3 * CHUNK);
            bulk_g2s(smem_u32(&stage[sn][0]),      w     + row, m);
            bulk_g2s(smem_u32(&stage[sn][TJ]),     alpha + row, m);
            bulk_g2s(smem_u32(&stage[sn][2 * TJ]), hebb  + row, m);
        }
    }

    const int j0 = cb * TJ + tid * 2;
#pragma unroll
    for (int b = 0; b < BB; b++) {
        float2 v = make_float2(accx[b], accy[b]);
        *(float2*)(g_scratch + ((size_t)rb * BB + b) * E + j0) = v;
    }
}

// ---------------------------------------------------------------------------
// K2 (parallel reduction): block owns 32 outputs; warp w sums 16 splits with
// coalesced loads; smem reduce; warp 0 adds input + tanh.
// ---------------------------------------------------------------------------
#define K2_OUTS 32
#define K2_SPW  (NSPLIT / 8)   // 16 splits per warp

__global__ __launch_bounds__(256)
void k2_yout(const float* __restrict__ input, float* __restrict__ yout)
{
    const int wid  = threadIdx.x >> 5;
    const int lane = threadIdx.x & 31;
    const int idx  = blockIdx.x * K2_OUTS + lane;

    float s = 0.f;
    const int r0 = wid * K2_SPW;
#pragma unroll
    for (int r = 0; r < K2_SPW; r++)
        s += g_scratch[(size_t)(r0 + r) * BB * E + idx];

    __shared__ float red[8][K2_OUTS];
    red[wid][lane] = s;
    __syncthreads();

    if (wid == 0) {
        float t = input[idx];
#pragma unroll
        for (int ww = 0; ww < 8; ww++)
            t += red[ww][lane];
        yout[idx] = tanhf(t);
    }
}

// ---------------------------------------------------------------------------
// K3: hebb_new = (1-eta)*hebb + eta * yin0 (outer) yout0 (128 MB stream).
// Reverse block order (MRU-first hebb) + __stcs output stores.
// ---------------------------------------------------------------------------
__global__ __launch_bounds__(256)
void k3_hebb(const float* __restrict__ hebb,
             const float* __restrict__ yin,
             const float* __restrict__ eta,
             const float* __restrict__ yout0,
             float* __restrict__ hebb_out)
{
    const float et    = eta[0];
    const float one_m = 1.0f - et;

    const int n4   = (E * E) / 4;
    const int rblk = gridDim.x - 1 - blockIdx.x;
    const int t    = rblk * 256 + threadIdx.x;
    if (t >= n4) return;

    const int row = t / (E / 4);
    const int c4  = t % (E / 4);
    const float s = et * yin[row];

    const float4 h = *(const float4*)(hebb + (size_t)t * 4);
    const float4 y = __ldg((const float4*)(yout0 + (size_t)c4 * 4));
    float4 o;
    o.x = fmaf(one_m, h.x, s * y.x);
    o.y = fmaf(one_m, h.y, s * y.y);
    o.z = fmaf(one_m, h.z, s * y.z);
    o.w = fmaf(one_m, h.w, s * y.w);
    __stcs((float4*)(hebb_out + (size_t)t * 4), o);
}

// ---------------------------------------------------------------------------
// Launch: inputs in metadata order: input, yin, hebb, w, alpha, eta
// Output: [yout (8*4096) | hebb_new (4096*4096)] fp32
// ---------------------------------------------------------------------------
extern "C" void kernel_launch(void* const* d_in, const int* in_sizes, int n_in,
                              void* d_out, int out_size)
{
    const float* input = (const float*)d_in[0];
    const float* yin   = (const float*)d_in[1];
    const float* hebb  = (const float*)d_in[2];
    const float* w     = (const float*)d_in[3];
    const float* alpha = (const float*)d_in[4];
    const float* eta   = (const float*)d_in[5];

    float* out      = (float*)d_out;
    float* yout     = out;            // BB*E
    float* hebb_out = out + BB * E;   // E*E

    dim3 g1(NCOLB, NSPLIT);           // 8 x 128 = 1024 blocks
    k1_partial_gemm<<<g1, 256>>>(yin, hebb, w, alpha);

    k2_yout<<<(BB * E) / K2_OUTS, 256>>>(input, yout);

    const int n4 = (E * E) / 4;
    k3_hebb<<<(n4 + 255) / 256, 256>>>(hebb, yin, eta, yout, hebb_out);
}

// round 15
// speedup vs baseline: 1.0627x; 1.0568x over previous
#include <cuda_runtime.h>
#include <math.h>

// Problem constants
#define E   4096
#define BB  8          // batch
#define TJ  512        // columns per block in K1 (256 threads * float2)
#define TK  32         // rows per split in K1 (best measured K1 shape)
#define NSPLIT (E / TK)   // 128 row-splits
#define NCOLB  (E / TJ)   // 8 column blocks

// Deterministic split-K scratch: [NSPLIT][BB][E] fp32 = 16 MB (evict-first)
__device__ float g_scratch[(size_t)NSPLIT * BB * E];

// ---------------------------------------------------------------------------
// K1 (converged shape, 38.9us): stream w/alpha/hebb once (192 MB).
// Block: 32 rows x 512 cols, float2/thread, 64 regs, 4 blocks/SM, grid=1024.
// w/alpha: __ldcs. hebb: plain cached, loaded LAST each iter (youngest fill).
// scratch: __stcs so scratch writes cannot evict hebb from L2 (K3 wants it).
// ---------------------------------------------------------------------------
__global__ __launch_bounds__(256, 4)
void k1_partial_gemm(const float* __restrict__ yin,
                     const float* __restrict__ hebb,
                     const float* __restrict__ w,
                     const float* __restrict__ alpha)
{
    const int cb  = blockIdx.x;            // 0..NCOLB-1
    const int rb  = blockIdx.y;            // 0..NSPLIT-1
    const int tid = threadIdx.x;           // 0..255
    const int j0  = cb * TJ + tid * 2;     // this thread's 2 columns
    const int k0  = rb * TK;

    // Stage yin[b, k0:k0+TK] in smem (8*32 = 256 floats, one per thread)
    __shared__ float yin_s[BB][TK];
    {
        int b = tid / TK, k = tid % TK;    // tid < 256 = BB*TK exactly
        yin_s[b][k] = yin[(size_t)b * E + k0 + k];
    }
    __syncthreads();

    float accx[BB], accy[BB];
#pragma unroll
    for (int b = 0; b < BB; b++) { accx[b] = 0.f; accy[b] = 0.f; }

    const size_t base0 = (size_t)k0 * E + j0;
    const float2* wp = (const float2*)(w     + base0);
    const float2* ap = (const float2*)(alpha + base0);
    const float2* hp = (const float2*)(hebb  + base0);
    const int strideV = E / 2;             // float2 row stride

    // Depth-2 pipeline: rows k and k+1 in flight
    float2 w0 = __ldcs(wp);
    float2 a0 = __ldcs(ap);
    float2 h0 = __ldg (hp);
    float2 w1 = __ldcs(wp + strideV);
    float2 a1 = __ldcs(ap + strideV);
    float2 h1 = __ldg (hp + strideV);

#pragma unroll 8
    for (int k = 0; k < TK; k++) {
        float2 wn, an, hn;
        if (k + 2 < TK) {
            const int off = (k + 2) * strideV;
            wn = __ldcs(wp + off);
            an = __ldcs(ap + off);
            hn = __ldg (hp + off);
        }

        const float mx = fmaf(a0.x, h0.x, w0.x);
        const float my = fmaf(a0.y, h0.y, w0.y);
#pragma unroll
        for (int b = 0; b < BB; b++) {
            const float yv = yin_s[b][k];
            accx[b] = fmaf(yv, mx, accx[b]);
            accy[b] = fmaf(yv, my, accy[b]);
        }

        w0 = w1; a0 = a1; h0 = h1;
        w1 = wn; a1 = an; h1 = hn;
    }

    // Evict-first scratch stores: preserve hebb's L2 residency for K3
#pragma unroll
    for (int b = 0; b < BB; b++) {
        float2 v = make_float2(accx[b], accy[b]);
        __stcs((float2*)(g_scratch + ((size_t)rb * BB + b) * E + j0), v);
    }
}

// ---------------------------------------------------------------------------
// K2 (parallel reduction): 1024 blocks x 256 threads.
// Block owns 32 consecutive outputs; warp w sums splits [w*16, w*16+16)
// with coalesced 128B loads; 8x32 smem reduce; warp 0 adds input + tanh.
// Scratch read with __ldcs (single use; don't displace hebb in L2).
// ---------------------------------------------------------------------------
#define K2_OUTS 32
#define K2_SPW  (NSPLIT / 8)   // 16 splits per warp

__global__ __launch_bounds__(256)
void k2_yout(const float* __restrict__ input, float* __restrict__ yout)
{
    const int wid  = threadIdx.x >> 5;         // 0..7
    const int lane = threadIdx.x & 31;         // 0..31
    const int idx  = blockIdx.x * K2_OUTS + lane;

    float s = 0.f;
    const int r0 = wid * K2_SPW;
#pragma unroll
    for (int r = 0; r < K2_SPW; r++)
        s += __ldcs(&g_scratch[(size_t)(r0 + r) * BB * E + idx]);

    __shared__ float red[8][K2_OUTS];
    red[wid][lane] = s;
    __syncthreads();

    if (wid == 0) {
        float t = input[idx];
#pragma unroll
        for (int ww = 0; ww < 8; ww++)
            t += red[ww][lane];
        yout[idx] = tanhf(t);
    }
}

// ---------------------------------------------------------------------------
// K3: hebb_new = (1-eta)*hebb + eta * yin0 (outer) yout0 (128 MB stream).
// Reverse block order (MRU-first hebb reads -> L2 hits from K1) + __stcs
// output stores (don't evict not-yet-read hebb lines).
// ---------------------------------------------------------------------------
__global__ __launch_bounds__(256)
void k3_hebb(const float* __restrict__ hebb,
             const float* __restrict__ yin,    // row 0 used
             const float* __restrict__ eta,    // scalar
             const float* __restrict__ yout0,  // d_out row 0 (E floats)
             float* __restrict__ hebb_out)
{
    const float et    = eta[0];
    const float one_m = 1.0f - et;

    const int n4   = (E * E) / 4;
    const int rblk = gridDim.x - 1 - blockIdx.x;      // reverse block order
    const int t    = rblk * 256 + threadIdx.x;        // one float4 per thread
    if (t >= n4) return;

    const int row = t / (E / 4);
    const int c4  = t % (E / 4);
    const float s = et * yin[row];                    // eta * yin0[row]

    const float4 h = *(const float4*)(hebb + (size_t)t * 4);   // L2 hits
    const float4 y = __ldg((const float4*)(yout0 + (size_t)c4 * 4));
    float4 o;
    o.x = fmaf(one_m, h.x, s * y.x);
    o.y = fmaf(one_m, h.y, s * y.y);
    o.z = fmaf(one_m, h.z, s * y.z);
    o.w = fmaf(one_m, h.w, s * y.w);
    __stcs((float4*)(hebb_out + (size_t)t * 4), o);
}

// ---------------------------------------------------------------------------
// Launch: inputs in metadata order: input, yin, hebb, w, alpha, eta
// Output: [yout (8*4096) | hebb_new (4096*4096)] fp32
// ---------------------------------------------------------------------------
extern "C" void kernel_launch(void* const* d_in, const int* in_sizes, int n_in,
                              void* d_out, int out_size)
{
    const float* input = (const float*)d_in[0];
    const float* yin   = (const float*)d_in[1];
    const float* hebb  = (const float*)d_in[2];
    const float* w     = (const float*)d_in[3];
    const float* alpha = (const float*)d_in[4];
    const float* eta   = (const float*)d_in[5];

    float* out      = (float*)d_out;
    float* yout     = out;            // BB*E
    float* hebb_out = out + BB * E;   // E*E

    // K1: 8 col-blocks x 128 row-splits = 1024 blocks x 256 threads
    dim3 g1(NCOLB, NSPLIT);
    k1_partial_gemm<<<g1, 256>>>(yin, hebb, w, alpha);

    // K2: 32768 outputs / 32 per block = 1024 blocks
    k2_yout<<<(BB * E) / K2_OUTS, 256>>>(input, yout);

    // K3: E*E/4 float4 threads, reverse-ordered blocks
    const int n4 = (E * E) / 4;
    k3_hebb<<<(n4 + 255) / 256, 256>>>(hebb, yin, eta, yout, hebb_out);
}

// round 16
// speedup vs baseline: 1.0684x; 1.0054x over previous
#include <cuda_runtime.h>
#include <math.h>

// Problem constants
#define E   4096
#define BB  8          // batch
#define TJ  512        // columns per block in K1 (256 threads * float2)
#define TK  64         // rows per split in K1 -> 8 MB scratch (L2-resident)
#define NSPLIT (E / TK)   // 64 row-splits
#define NCOLB  (E / TJ)   // 8 column blocks

// Deterministic split-K scratch: [NSPLIT][BB][E] fp32 = 8 MB
__device__ float g_scratch[(size_t)NSPLIT * BB * E];

// ---------------------------------------------------------------------------
// K1 (R5 exact shape): stream w/alpha/hebb once (192 MB).
// Block: 64 rows x 512 cols, float2/thread, 64 regs, 4 blocks/SM, grid=512.
// w/alpha: __ldcs (evict-first). scratch: plain cached (stays in L2 for K2).
// ---------------------------------------------------------------------------
__global__ __launch_bounds__(256, 4)
void k1_partial_gemm(const float* __restrict__ yin,
                     const float* __restrict__ hebb,
                     const float* __restrict__ w,
                     const float* __restrict__ alpha)
{
    const int cb  = blockIdx.x;            // 0..NCOLB-1
    const int rb  = blockIdx.y;            // 0..NSPLIT-1
    const int tid = threadIdx.x;           // 0..255
    const int j0  = cb * TJ + tid * 2;     // this thread's 2 columns
    const int k0  = rb * TK;

    // Stage yin[b, k0:k0+TK] in smem
    __shared__ float yin_s[BB][TK];
    for (int i = tid; i < BB * TK; i += 256) {
        int b = i / TK, k = i % TK;
        yin_s[b][k] = yin[(size_t)b * E + k0 + k];
    }
    __syncthreads();

    float accx[BB], accy[BB];
#pragma unroll
    for (int b = 0; b < BB; b++) { accx[b] = 0.f; accy[b] = 0.f; }

    const size_t base0 = (size_t)k0 * E + j0;
    const float2* wp = (const float2*)(w     + base0);
    const float2* ap = (const float2*)(alpha + base0);
    const float2* hp = (const float2*)(hebb  + base0);
    const int strideV = E / 2;             // float2 row stride

    // Depth-2 pipeline: rows k and k+1 in flight
    float2 w0 = __ldcs(wp);
    float2 a0 = __ldcs(ap);
    float2 h0 = __ldg (hp);
    float2 w1 = __ldcs(wp + strideV);
    float2 a1 = __ldcs(ap + strideV);
    float2 h1 = __ldg (hp + strideV);

#pragma unroll 8
    for (int k = 0; k < TK; k++) {
        float2 wn, an, hn;
        if (k + 2 < TK) {
            const int off = (k + 2) * strideV;
            wn = __ldcs(wp + off);
            an = __ldcs(ap + off);
            hn = __ldg (hp + off);
        }

        const float mx = fmaf(a0.x, h0.x, w0.x);
        const float my = fmaf(a0.y, h0.y, w0.y);
#pragma unroll
        for (int b = 0; b < BB; b++) {
            const float yv = yin_s[b][k];
            accx[b] = fmaf(yv, mx, accx[b]);
            accy[b] = fmaf(yv, my, accy[b]);
        }

        w0 = w1; a0 = a1; h0 = h1;
        w1 = wn; a1 = an; h1 = hn;
    }

    // Plain cached stores: 8 MB scratch stays L2-resident for K2
#pragma unroll
    for (int b = 0; b < BB; b++) {
        float2 v = make_float2(accx[b], accy[b]);
        *(float2*)(g_scratch + ((size_t)rb * BB + b) * E + j0) = v;
    }
}

// ---------------------------------------------------------------------------
// K2 (parallel reduction, NSPLIT=64): 1024 blocks x 256 threads.
// Block owns 32 consecutive outputs; warp w sums splits [w*8, w*8+8)
// with coalesced 128B loads; 8x32 smem reduce; warp 0 adds input + tanh.
// ---------------------------------------------------------------------------
#define K2_OUTS 32
#define K2_SPW  (NSPLIT / 8)   // 8 splits per warp

__global__ __launch_bounds__(256)
void k2_yout(const float* __restrict__ input, float* __restrict__ yout)
{
    const int wid  = threadIdx.x >> 5;         // 0..7
    const int lane = threadIdx.x & 31;         // 0..31
    const int idx  = blockIdx.x * K2_OUTS + lane;

    float s = 0.f;
    const int r0 = wid * K2_SPW;
#pragma unroll
    for (int r = 0; r < K2_SPW; r++)
        s += g_scratch[(size_t)(r0 + r) * BB * E + idx];

    __shared__ float red[8][K2_OUTS];
    red[wid][lane] = s;
    __syncthreads();

    if (wid == 0) {
        float t = input[idx];
#pragma unroll
        for (int ww = 0; ww < 8; ww++)
            t += red[ww][lane];
        yout[idx] = tanhf(t);
    }
}

// ---------------------------------------------------------------------------
// K3 (R9 winner): hebb_new = (1-eta)*hebb + eta * yin0 (outer) yout0.
// Reverse block order (MRU-first hebb reads) + __stcs output stores.
// ---------------------------------------------------------------------------
__global__ __launch_bounds__(256)
void k3_hebb(const float* __restrict__ hebb,
             const float* __restrict__ yin,    // row 0 used
             const float* __restrict__ eta,    // scalar
             const float* __restrict__ yout0,  // d_out row 0 (E floats)
             float* __restrict__ hebb_out)
{
    const float et    = eta[0];
    const float one_m = 1.0f - et;

    const int n4   = (E * E) / 4;
    const int rblk = gridDim.x - 1 - blockIdx.x;      // reverse block order
    const int t    = rblk * 256 + threadIdx.x;        // one float4 per thread
    if (t >= n4) return;

    const int row = t / (E / 4);
    const int c4  = t % (E / 4);
    const float s = et * yin[row];                    // eta * yin0[row]

    const float4 h = *(const float4*)(hebb + (size_t)t * 4);
    const float4 y = __ldg((const float4*)(yout0 + (size_t)c4 * 4));
    float4 o;
    o.x = fmaf(one_m, h.x, s * y.x);
    o.y = fmaf(one_m, h.y, s * y.y);
    o.z = fmaf(one_m, h.z, s * y.z);
    o.w = fmaf(one_m, h.w, s * y.w);
    __stcs((float4*)(hebb_out + (size_t)t * 4), o);
}

// ---------------------------------------------------------------------------
// Launch: inputs in metadata order: input, yin, hebb, w, alpha, eta
// Output: [yout (8*4096) | hebb_new (4096*4096)] fp32
// ---------------------------------------------------------------------------
extern "C" void kernel_launch(void* const* d_in, const int* in_sizes, int n_in,
                              void* d_out, int out_size)
{
    const float* input = (const float*)d_in[0];
    const float* yin   = (const float*)d_in[1];
    const float* hebb  = (const float*)d_in[2];
    const float* w     = (const float*)d_in[3];
    const float* alpha = (const float*)d_in[4];
    const float* eta   = (const float*)d_in[5];

    float* out      = (float*)d_out;
    float* yout     = out;            // BB*E
    float* hebb_out = out + BB * E;   // E*E

    // K1: 8 col-blocks x 64 row-splits = 512 blocks x 256 threads
    dim3 g1(NCOLB, NSPLIT);
    k1_partial_gemm<<<g1, 256>>>(yin, hebb, w, alpha);

    // K2: 32768 outputs / 32 per block = 1024 blocks
    k2_yout<<<(BB * E) / K2_OUTS, 256>>>(input, yout);

    // K3: E*E/4 float4 threads, reverse-ordered blocks
    const int n4 = (E * E) / 4;
    k3_hebb<<<(n4 + 255) / 256, 256>>>(hebb, yin, eta, yout, hebb_out);
}